// round 14
// baseline (speedup 1.0000x reference)
#include <cuda_runtime.h>

#define NB 64
#define NL 512
#define TILES 16
#define ROWS (NL / TILES)      // 32 i-rows per block
#define NTHREADS 128
#define NBLOCKS (NB * TILES)   // 1024

__device__ float g_sqrtsum[NBLOCKS];
__device__ float g_closed[NB];
__device__ float g_res[NB];
__device__ unsigned int g_cnt_batch[NB];   // zero-init; reset each replay
__device__ unsigned int g_cnt_final;       // zero-init; reset each replay

__device__ __forceinline__ float sqrt_approx(float x) {
    float r; asm("sqrt.approx.f32 %0, %1;" : "=f"(r) : "f"(x)); return r;
}

// Full i,j matrix sum == 2 * triangle (diagonal ~0).  Per pair (Gram form):
//   err = s1 + s2 - 2*sqrt(s1*s2),  s = n_i + n_j - 2<x_i,x_j>
// Closed form (exact, O(L)): sum_{i,j}(s1+s2) = 2L*Sum(n) - 2|Sum(x)|^2 per field.
// => 2*sumsq_tri = closed - 2 * sum_full sqrt(s1*s2).
// Each thread owns 4 j-columns -> 2 broadcast LDS.128 serve 4 pair-evals.
__global__ void __launch_bounds__(NTHREADS, 8) fused_kernel(
    const float* __restrict__ inp, const float* __restrict__ tgt,
    float* __restrict__ out)
{
    __shared__ float4 sIn[NL];
    __shared__ float4 sTg[NL];
    __shared__ float swarp[4];
    __shared__ float sred[4][8];

    const int b   = blockIdx.x / TILES;
    const int t   = blockIdx.x % TILES;
    const int tid = threadIdx.x;

    // ---- stage CA coords + norms (atom 1 -> floats 3..5 of 9/residue)
    for (int k = tid; k < NL; k += NTHREADS) {
        int base = (b * NL + k) * 9 + 3;
        float ax = inp[base + 0], ay = inp[base + 1], az = inp[base + 2];
        float cx = tgt[base + 0], cy = tgt[base + 1], cz = tgt[base + 2];
        sIn[k] = make_float4(ax, ay, az, fmaf(ax, ax, fmaf(ay, ay, az * az)));
        sTg[k] = make_float4(cx, cy, cz, fmaf(cx, cx, fmaf(cy, cy, cz * cz)));
    }
    __syncthreads();

    // ---- batch stats (tile-0 blocks): Sum(x), Sum(n) -> closed form
    if (t == 0) {
        float4 pI = make_float4(0.f, 0.f, 0.f, 0.f), pT = pI;
#pragma unroll
        for (int q = 0; q < 4; ++q) {
            float4 a = sIn[tid + q * NTHREADS];
            pI.x += a.x; pI.y += a.y; pI.z += a.z; pI.w += a.w;
            float4 c = sTg[tid + q * NTHREADS];
            pT.x += c.x; pT.y += c.y; pT.z += c.z; pT.w += c.w;
        }
        for (int off = 16; off > 0; off >>= 1) {
            pI.x += __shfl_down_sync(0xFFFFFFFFu, pI.x, off);
            pI.y += __shfl_down_sync(0xFFFFFFFFu, pI.y, off);
            pI.z += __shfl_down_sync(0xFFFFFFFFu, pI.z, off);
            pI.w += __shfl_down_sync(0xFFFFFFFFu, pI.w, off);
            pT.x += __shfl_down_sync(0xFFFFFFFFu, pT.x, off);
            pT.y += __shfl_down_sync(0xFFFFFFFFu, pT.y, off);
            pT.z += __shfl_down_sync(0xFFFFFFFFu, pT.z, off);
            pT.w += __shfl_down_sync(0xFFFFFFFFu, pT.w, off);
        }
        if ((tid & 31) == 0) {
            int w = tid >> 5;
            sred[w][0] = pI.x; sred[w][1] = pI.y; sred[w][2] = pI.z; sred[w][3] = pI.w;
            sred[w][4] = pT.x; sred[w][5] = pT.y; sred[w][6] = pT.z; sred[w][7] = pT.w;
        }
        __syncthreads();
        if (tid == 0) {
            float v[8];
#pragma unroll
            for (int q = 0; q < 8; ++q)
                v[q] = sred[0][q] + sred[1][q] + sred[2][q] + sred[3][q];
            float c1 = 2.0f * NL * v[3] - 2.0f * (v[0]*v[0] + v[1]*v[1] + v[2]*v[2]);
            float c2 = 2.0f * NL * v[7] - 2.0f * (v[4]*v[4] + v[5]*v[5] + v[6]*v[6]);
            g_closed[b] = c1 + c2;
        }
    }

    // ---- 4 j-columns per thread, coords prescaled by -2
    float ax[4], ay[4], az[4], nn[4];
    float cx[4], cy[4], cz[4], mm[4];
#pragma unroll
    for (int q = 0; q < 4; ++q) {
        float4 Ji = sIn[tid + q * NTHREADS];
        float4 Jt = sTg[tid + q * NTHREADS];
        ax[q] = -2.f * Ji.x; ay[q] = -2.f * Ji.y; az[q] = -2.f * Ji.z; nn[q] = Ji.w;
        cx[q] = -2.f * Jt.x; cy[q] = -2.f * Jt.y; cz[q] = -2.f * Jt.z; mm[q] = Jt.w;
    }

    float acc[4] = {0.f, 0.f, 0.f, 0.f};

    const int i0 = t * ROWS;
#pragma unroll 4
    for (int i = i0; i < i0 + ROWS; ++i) {
        const float4 I = sIn[i];   // broadcast LDS.128
        const float4 T = sTg[i];
#pragma unroll
        for (int q = 0; q < 4; ++q) {
            float s1 = fmaf(I.x, ax[q], fmaf(I.y, ay[q], fmaf(I.z, az[q], I.w))) + nn[q];
            float s2 = fmaf(T.x, cx[q], fmaf(T.y, cy[q], fmaf(T.z, cz[q], T.w))) + mm[q];
            acc[q] += sqrt_approx(fabsf(s1 * s2));
        }
    }

    float r = (acc[0] + acc[1]) + (acc[2] + acc[3]);

    // ---- block reduce (4 warps)
    for (int off = 16; off > 0; off >>= 1)
        r += __shfl_down_sync(0xFFFFFFFFu, r, off);
    if ((tid & 31) == 0) swarp[tid >> 5] = r;
    __syncthreads();

    // ---- two-level epilogue ----
    if (tid == 0) {
        g_sqrtsum[blockIdx.x] = (swarp[0] + swarp[1]) + (swarp[2] + swarp[3]);
        __threadfence();
        unsigned int old = atomicAdd(&g_cnt_batch[b], 1u);
        if (old == TILES - 1) {
            float sq = 0.0f;                     // fixed order -> deterministic
#pragma unroll
            for (int k = 0; k < TILES; ++k)
                sq += g_sqrtsum[b * TILES + k];
            float total = g_closed[b] - 2.0f * sq;   // == 2 * sumsq_tri
            float res = sqrtf(total + 1e-6f);
            res *= (1.0f / (sqrtf((float)NL * (float)(NL - 1)) * (float)NL));
            g_res[b] = res;
            g_cnt_batch[b] = 0;
            __threadfence();
            unsigned int o2 = atomicAdd(&g_cnt_final, 1u);
            if (o2 == NB - 1) {
                float s = 0.0f;
#pragma unroll
                for (int bb = 0; bb < NB; ++bb) s += g_res[bb];
                out[0] = s * (1.0f / (float)NB);
                g_cnt_final = 0;
            }
        }
    }
}

extern "C" void kernel_launch(void* const* d_in, const int* in_sizes, int n_in,
                              void* d_out, int out_size)
{
    const float* inp = (const float*)d_in[0];
    const float* tgt = (const float*)d_in[1];
    float* out = (float*)d_out;
    fused_kernel<<<NBLOCKS, NTHREADS>>>(inp, tgt, out);
}

// round 15
// speedup vs baseline: 1.0105x; 1.0105x over previous
#include <cuda_runtime.h>

#define NB 64
#define NL 512
#define TS 64                  // tile size
#define NT (NL / TS)           // 8 tiles
#define NUNITS 36              // 8 diag + 28 rect
#define NTHREADS 128
#define NBLOCKS (NB * NUNITS)  // 2304
#define TILE_F4 144            // 64 pts * 9 floats / 4 = 144 float4 per raw tile

__device__ float g_sqrtsum[NBLOCKS];
__device__ float g_stats[NB * NT * 8];
__device__ float g_res[NB];
__device__ unsigned int g_cnt_batch[NB];   // zero-init; reset each replay
__device__ unsigned int g_cnt_final;       // zero-init; reset each replay

__device__ __forceinline__ float sqrt_approx(float x) {
    float r; asm("sqrt.approx.f32 %0, %1;" : "=f"(r) : "f"(x)); return r;
}

// 64-wide tiled triangle: diag units (t,t) weight 1/2, rect units (tj<ti)
// weight 1.  Per pair (Gram): err = s1+s2-2*sqrt(s1*s2).
// Closed form via per-tile partials: sum(s1+s2) = 2L*Sum(n)-2|Sum(x)|^2/field.
// 2*sumsq_tri = closed - 4*sqrtsum_tri.
// Staging is COALESCED: raw tile (2.25KB) copied as aligned float4s, CA+norm
// extracted from smem (stride-9 LDS, gcd(9,32)=1 -> conflict-free).
__global__ void __launch_bounds__(NTHREADS) fused_kernel(
    const float* __restrict__ inp, const float* __restrict__ tgt,
    float* __restrict__ out)
{
    __shared__ float4 raw[4 * TILE_F4];    // [J_in | J_tg | I_in | I_tg]
    __shared__ float4 sJ[TS], sJt[TS];
    __shared__ float4 sI[TS], sIt[TS];
    __shared__ float  swarp[4];
    __shared__ float  sst[2][8];

    const int b   = blockIdx.x / NUNITS;
    const int u   = blockIdx.x % NUNITS;
    const int tid = threadIdx.x;

    int tj, ti;
    if (u < NT) { tj = u; ti = u; }
    else {
        int rem = u - NT;
        tj = 0;
        while (rem >= NT - 1 - tj) { rem -= NT - 1 - tj; ++tj; }
        ti = tj + 1 + rem;
    }
    const bool diag = (u < NT);
    const float w = diag ? 0.5f : 1.0f;

    // ---- coalesced raw staging (float4-aligned: tile offset = 576*t floats)
    {
        const float4* J_in = (const float4*)(inp + ((size_t)b * NL + tj * TS) * 9);
        const float4* J_tg = (const float4*)(tgt + ((size_t)b * NL + tj * TS) * 9);
        for (int k = tid; k < TILE_F4; k += NTHREADS) {
            raw[k]           = J_in[k];
            raw[TILE_F4 + k] = J_tg[k];
        }
        if (!diag) {
            const float4* I_in = (const float4*)(inp + ((size_t)b * NL + ti * TS) * 9);
            const float4* I_tg = (const float4*)(tgt + ((size_t)b * NL + ti * TS) * 9);
            for (int k = tid; k < TILE_F4; k += NTHREADS) {
                raw[2 * TILE_F4 + k] = I_in[k];
                raw[3 * TILE_F4 + k] = I_tg[k];
            }
        }
    }
    __syncthreads();

    // ---- extract CA coords + norms (atom 1 -> floats 3..5 of 9/residue)
    {
        const float* rf = (const float*)raw;
        int lp  = tid & 63;
        int seg = tid >> 6;                        // 0 = input, 1 = target
        const float* s0 = rf + seg * (TILE_F4 * 4);
        float x = s0[lp * 9 + 3], y = s0[lp * 9 + 4], z = s0[lp * 9 + 5];
        float4 v = make_float4(x, y, z, fmaf(x, x, fmaf(y, y, z * z)));
        if (seg == 0) sJ[lp] = v; else sJt[lp] = v;
        if (!diag) {
            const float* s1 = rf + 2 * (TILE_F4 * 4) + seg * (TILE_F4 * 4);
            float x2 = s1[lp * 9 + 3], y2 = s1[lp * 9 + 4], z2 = s1[lp * 9 + 5];
            float4 v2 = make_float4(x2, y2, z2, fmaf(x2, x2, fmaf(y2, y2, z2 * z2)));
            if (seg == 0) sI[lp] = v2; else sIt[lp] = v2;
        }
    }
    __syncthreads();

    // ---- per-tile stats (diag blocks): sums over this tile's 64 points
    if (diag) {
        int lp = tid & 63;
        float4 a = (tid < 64) ? sJ[lp] : sJt[lp];
        float v0 = a.x, v1 = a.y, v2 = a.z, v3 = a.w;
        for (int off = 16; off > 0; off >>= 1) {
            v0 += __shfl_down_sync(0xFFFFFFFFu, v0, off);
            v1 += __shfl_down_sync(0xFFFFFFFFu, v1, off);
            v2 += __shfl_down_sync(0xFFFFFFFFu, v2, off);
            v3 += __shfl_down_sync(0xFFFFFFFFu, v3, off);
        }
        if ((tid & 31) == 0) {
            int g = tid >> 6;                      // 0 = input, 1 = target
            int hw = (tid >> 5) & 1;
            if (hw == 0) { sst[g][0] = v0; sst[g][1] = v1; sst[g][2] = v2; sst[g][3] = v3; }
            else         { sst[g][4] = v0; sst[g][5] = v1; sst[g][6] = v2; sst[g][7] = v3; }
        }
        __syncthreads();
        if (tid < 8) {
            int g = tid >> 2, q = tid & 3;
            g_stats[(b * NT + u) * 8 + g * 4 + q] = sst[g][q] + sst[g][q + 4];
        }
    }

    // ---- inner loop: thread owns j = tj*64 + (tid&63), i-half by tid>>6
    const int lj = tid & 63;
    const float4 J = sJ[lj], Jt = sJt[lj];
    const float ax = -2.f * J.x,  ay = -2.f * J.y,  az = -2.f * J.z,  n0 = J.w;
    const float cx = -2.f * Jt.x, cy = -2.f * Jt.y, cz = -2.f * Jt.z, m0 = Jt.w;

    const float4* Ib = diag ? sJ  : sI;
    const float4* Tb = diag ? sJt : sIt;
    const int i0 = (tid >> 6) * 32;

    float acc = 0.0f;
#pragma unroll 8
    for (int i = i0; i < i0 + 32; ++i) {
        const float4 I = Ib[i];                    // broadcast LDS.128
        const float4 T = Tb[i];
        float s1 = fmaf(I.x, ax, fmaf(I.y, ay, fmaf(I.z, az, I.w))) + n0;
        float s2 = fmaf(T.x, cx, fmaf(T.y, cy, fmaf(T.z, cz, T.w))) + m0;
        acc += sqrt_approx(fabsf(s1 * s2));
    }
    acc *= w;

    // ---- block reduce (4 warps)
    for (int off = 16; off > 0; off >>= 1)
        acc += __shfl_down_sync(0xFFFFFFFFu, acc, off);
    __syncthreads();
    if ((tid & 31) == 0) swarp[tid >> 5] = acc;
    __syncthreads();

    // ---- two-level epilogue ----
    if (tid == 0) {
        g_sqrtsum[blockIdx.x] = (swarp[0] + swarp[1]) + (swarp[2] + swarp[3]);
        __threadfence();
        unsigned int old = atomicAdd(&g_cnt_batch[b], 1u);
        if (old == NUNITS - 1) {
            float v[8];
#pragma unroll
            for (int q = 0; q < 8; ++q) {
                float s = 0.0f;
#pragma unroll
                for (int t = 0; t < NT; ++t)       // fixed-order tile combine
                    s += g_stats[(b * NT + t) * 8 + q];
                v[q] = s;
            }
            float c1 = 2.0f * NL * v[3] - 2.0f * (v[0]*v[0] + v[1]*v[1] + v[2]*v[2]);
            float c2 = 2.0f * NL * v[7] - 2.0f * (v[4]*v[4] + v[5]*v[5] + v[6]*v[6]);
            float sq = 0.0f;                       // fixed-order sqrt-sum
#pragma unroll
            for (int k = 0; k < NUNITS; ++k)
                sq += g_sqrtsum[b * NUNITS + k];
            float total = (c1 + c2) - 4.0f * sq;   // == 2 * sumsq_tri
            float res = sqrtf(total + 1e-6f);
            res *= (1.0f / (sqrtf((float)NL * (float)(NL - 1)) * (float)NL));
            g_res[b] = res;
            g_cnt_batch[b] = 0;
            __threadfence();
            unsigned int o2 = atomicAdd(&g_cnt_final, 1u);
            if (o2 == NB - 1) {
                float s = 0.0f;
#pragma unroll
                for (int bb = 0; bb < NB; ++bb) s += g_res[bb];
                out[0] = s * (1.0f / (float)NB);
                g_cnt_final = 0;
            }
        }
    }
}

extern "C" void kernel_launch(void* const* d_in, const int* in_sizes, int n_in,
                              void* d_out, int out_size)
{
    const float* inp = (const float*)d_in[0];
    const float* tgt = (const float*)d_in[1];
    float* out = (float*)d_out;
    fused_kernel<<<NBLOCKS, NTHREADS>>>(inp, tgt, out);
}

// round 16
// speedup vs baseline: 1.1292x; 1.1174x over previous
#include <cuda_runtime.h>
#include <cuda_fp16.h>

#define NB 64
#define NL 512
#define TS 64                  // tile size
#define NT (NL / TS)           // 8 tiles
#define NUNITS 36              // 8 diag + 28 rect
#define NTHREADS 128
#define NBLOCKS (NB * NUNITS)  // 2304

__device__ float g_sqrtsum[NBLOCKS];
__device__ float g_stats[NB * NT * 8];
__device__ float g_res[NB];
__device__ unsigned int g_cnt_batch[NB];   // zero-init; reset each replay
__device__ unsigned int g_cnt_final;       // zero-init; reset each replay

__device__ __forceinline__ float sqrt_approx(float x) {
    float r; asm("sqrt.approx.f32 %0, %1;" : "=f"(r) : "f"(x)); return r;
}
__device__ __forceinline__ __half2 u2h(unsigned int u) {
    __half2 h; *reinterpret_cast<unsigned int*>(&h) = u; return h;
}
__device__ __forceinline__ unsigned int h2u(__half2 h) {
    return *reinterpret_cast<unsigned int*>(&h);
}

// 64-wide tiled triangle (R12 skeleton): diag units (t,t) weight 1/2, rect
// units (tj<ti) weight 1.  2*sumsq_tri = closed - 4*sqrtsum_tri, closed form
// per-tile in EXACT fp32: sum(s1+s2) = 2L*Sum(n) - 2|Sum(x)|^2 per field.
// NEW: points stored as half2-packed {input,target}: one uint4 {X2,Y2,Z2,N2}
// per point; one HFMA2 chain computes both tensors' s at once ->
// ~10 issues/pair instead of ~18, 1 LDS.128/pair instead of 2.
__global__ void __launch_bounds__(NTHREADS) fused_kernel(
    const float* __restrict__ inp, const float* __restrict__ tgt,
    float* __restrict__ out)
{
    __shared__ uint4 sJ[TS];               // j-tile, half2-packed
    __shared__ uint4 sI[TS];               // i-tile (rect only)
    __shared__ float swarp[4];
    __shared__ float sst[2][8];

    const int b   = blockIdx.x / NUNITS;
    const int u   = blockIdx.x % NUNITS;
    const int tid = threadIdx.x;

    int tj, ti;
    if (u < NT) { tj = u; ti = u; }
    else {
        int rem = u - NT;
        tj = 0;
        while (rem >= NT - 1 - tj) { rem -= NT - 1 - tj; ++tj; }
        ti = tj + 1 + rem;
    }
    const bool diag = (u < NT);
    const float w = diag ? 0.5f : 1.0f;

    // ---- staging: thread <64 stages j-tile point (both tensors, fp32->half2);
    //      thread >=64 stages i-tile point (rect only).  fp32 kept for stats.
    float xi = 0.f, yi = 0.f, zi = 0.f, ni = 0.f;
    float xt = 0.f, yt = 0.f, zt = 0.f, nt = 0.f;
    if (tid < 64) {
        int p = (b * NL + tj * TS + tid) * 9 + 3;
        xi = inp[p]; yi = inp[p + 1]; zi = inp[p + 2];
        xt = tgt[p]; yt = tgt[p + 1]; zt = tgt[p + 2];
        ni = fmaf(xi, xi, fmaf(yi, yi, zi * zi));
        nt = fmaf(xt, xt, fmaf(yt, yt, zt * zt));
        uint4 v;
        v.x = h2u(__floats2half2_rn(xi, xt));
        v.y = h2u(__floats2half2_rn(yi, yt));
        v.z = h2u(__floats2half2_rn(zi, zt));
        v.w = h2u(__floats2half2_rn(ni, nt));
        sJ[tid] = v;
    } else if (!diag) {
        int lp = tid - 64;
        int p = (b * NL + ti * TS + lp) * 9 + 3;
        float a0 = inp[p], a1 = inp[p + 1], a2 = inp[p + 2];
        float c0 = tgt[p], c1 = tgt[p + 1], c2 = tgt[p + 2];
        uint4 v;
        v.x = h2u(__floats2half2_rn(a0, c0));
        v.y = h2u(__floats2half2_rn(a1, c1));
        v.z = h2u(__floats2half2_rn(a2, c2));
        v.w = h2u(__floats2half2_rn(fmaf(a0, a0, fmaf(a1, a1, a2 * a2)),
                                    fmaf(c0, c0, fmaf(c1, c1, c2 * c2))));
        sI[lp] = v;
    }
    __syncthreads();

    // ---- per-tile fp32 stats (diag blocks, warps 0-1 hold the tile's points)
    if (diag && tid < 64) {
        float v0 = xi, v1 = yi, v2 = zi, v3 = ni;
        float v4 = xt, v5 = yt, v6 = zt, v7 = nt;
        for (int off = 16; off > 0; off >>= 1) {
            v0 += __shfl_down_sync(0xFFFFFFFFu, v0, off);
            v1 += __shfl_down_sync(0xFFFFFFFFu, v1, off);
            v2 += __shfl_down_sync(0xFFFFFFFFu, v2, off);
            v3 += __shfl_down_sync(0xFFFFFFFFu, v3, off);
            v4 += __shfl_down_sync(0xFFFFFFFFu, v4, off);
            v5 += __shfl_down_sync(0xFFFFFFFFu, v5, off);
            v6 += __shfl_down_sync(0xFFFFFFFFu, v6, off);
            v7 += __shfl_down_sync(0xFFFFFFFFu, v7, off);
        }
        if ((tid & 31) == 0) {
            int wp = tid >> 5;
            sst[wp][0] = v0; sst[wp][1] = v1; sst[wp][2] = v2; sst[wp][3] = v3;
            sst[wp][4] = v4; sst[wp][5] = v5; sst[wp][6] = v6; sst[wp][7] = v7;
        }
    }
    __syncthreads();
    if (diag && tid < 8)
        g_stats[(b * NT + u) * 8 + tid] = sst[0][tid] + sst[1][tid];

    // ---- j-constants: thread owns j = tid&63, prescaled by -2 (exact)
    const int lj = tid & 63;
    const uint4 jv = sJ[lj];
    const __half2 NEG2 = __floats2half2_rn(-2.0f, -2.0f);
    const __half2 Xj = __hmul2(u2h(jv.x), NEG2);
    const __half2 Yj = __hmul2(u2h(jv.y), NEG2);
    const __half2 Zj = __hmul2(u2h(jv.z), NEG2);
    const __half2 Nj = u2h(jv.w);

    const uint4* Ib = diag ? sJ : sI;
    const int i0 = (tid >> 6) * 32;

    float acc = 0.0f;
#pragma unroll 8
    for (int i = i0; i < i0 + 32; ++i) {
        const uint4 iv = Ib[i];            // ONE broadcast LDS.128, both tensors
        __half2 g = __hfma2(u2h(iv.x), Xj,
                    __hfma2(u2h(iv.y), Yj,
                    __hfma2(u2h(iv.z), Zj, u2h(iv.w))));
        __half2 s = __hadd2(g, Nj);        // {s_in, s_tg}
        float2 f = __half22float2(s);
        acc += sqrt_approx(fabsf(f.x * f.y));
    }
    acc *= w;

    // ---- block reduce (4 warps)
    for (int off = 16; off > 0; off >>= 1)
        acc += __shfl_down_sync(0xFFFFFFFFu, acc, off);
    __syncthreads();
    if ((tid & 31) == 0) swarp[tid >> 5] = acc;
    __syncthreads();

    // ---- two-level epilogue ----
    if (tid == 0) {
        g_sqrtsum[blockIdx.x] = (swarp[0] + swarp[1]) + (swarp[2] + swarp[3]);
        __threadfence();
        unsigned int old = atomicAdd(&g_cnt_batch[b], 1u);
        if (old == NUNITS - 1) {
            float v[8];
#pragma unroll
            for (int q = 0; q < 8; ++q) {
                float s = 0.0f;
#pragma unroll
                for (int t = 0; t < NT; ++t)       // fixed-order tile combine
                    s += g_stats[(b * NT + t) * 8 + q];
                v[q] = s;
            }
            float c1 = 2.0f * NL * v[3] - 2.0f * (v[0]*v[0] + v[1]*v[1] + v[2]*v[2]);
            float c2 = 2.0f * NL * v[7] - 2.0f * (v[4]*v[4] + v[5]*v[5] + v[6]*v[6]);
            float sq = 0.0f;                       // fixed-order sqrt-sum
#pragma unroll
            for (int k = 0; k < NUNITS; ++k)
                sq += g_sqrtsum[b * NUNITS + k];
            float total = (c1 + c2) - 4.0f * sq;   // == 2 * sumsq_tri
            float res = sqrtf(total + 1e-6f);
            res *= (1.0f / (sqrtf((float)NL * (float)(NL - 1)) * (float)NL));
            g_res[b] = res;
            g_cnt_batch[b] = 0;
            __threadfence();
            unsigned int o2 = atomicAdd(&g_cnt_final, 1u);
            if (o2 == NB - 1) {
                float s = 0.0f;
#pragma unroll
                for (int bb = 0; bb < NB; ++bb) s += g_res[bb];
                out[0] = s * (1.0f / (float)NB);
                g_cnt_final = 0;
            }
        }
    }
}

extern "C" void kernel_launch(void* const* d_in, const int* in_sizes, int n_in,
                              void* d_out, int out_size)
{
    const float* inp = (const float*)d_in[0];
    const float* tgt = (const float*)d_in[1];
    float* out = (float*)d_out;
    fused_kernel<<<NBLOCKS, NTHREADS>>>(inp, tgt, out);
}